// round 15
// baseline (speedup 1.0000x reference)
#include <cuda_runtime.h>
#include <cuda_bf16.h>
#include <cstdint>

// Problem constants
#define B_    32
#define L_    4096
#define C_    64
#define PL_   64
#define PC_   16
#define NP_   256
#define OUT_  512
#define DIN   2048              // PL * 2*PC (original w1 inner dim)
#define M_TOT 8192              // B * NP
#define K1    1088              // PL*PC (patch) + PL (folded time feature)
#define KPATCH 1024             // PL*PC

// ---------------- device scratch (no allocations allowed) ----------------
__device__ __nv_bfloat16 g_w1h[OUT_ * K1];
__device__ __nv_bfloat16 g_w1l[OUT_ * K1];
__device__ __nv_bfloat16 g_w2h[OUT_ * OUT_];
__device__ __nv_bfloat16 g_w2l[OUT_ * OUT_];
__device__ __nv_bfloat16 g_fh[M_TOT * K1];
__device__ __nv_bfloat16 g_fl[M_TOT * K1];
__device__ __nv_bfloat16 g_hh[M_TOT * OUT_];
__device__ __nv_bfloat16 g_hl[M_TOT * OUT_];

__device__ __forceinline__ void split_bf16(float v, __nv_bfloat16& hi, __nv_bfloat16& lo) {
    hi = __float2bfloat16(v);                       // RN
    lo = __float2bfloat16(v - __bfloat162float(hi)); // residual (exact subtract)
}

// ---------------- weight prep: fold time columns, split hi/lo ----------------
__global__ void prep_w1_kernel(const float* __restrict__ w1) {
    int idx = blockIdx.x * 256 + threadIdx.x;
    if (idx >= OUT_ * K1) return;
    int o = idx / K1;
    int k = idx - o * K1;
    float v;
    if (k < KPATCH) {
        int l = k >> 4, c = k & 15;
        v = w1[o * DIN + l * 32 + c];
    } else {
        int l = k - KPATCH;
        const float* p = w1 + o * DIN + l * 32 + 16;
        float s = 0.f;
#pragma unroll
        for (int c = 0; c < 16; ++c) s += p[c];
        v = s;
    }
    split_bf16(v, g_w1h[idx], g_w1l[idx]);
}

__global__ void prep_w2_kernel(const float* __restrict__ w2) {
    int idx = blockIdx.x * 256 + threadIdx.x;
    if (idx >= OUT_ * OUT_) return;
    split_bf16(w2[idx], g_w2h[idx], g_w2l[idx]);
}

// ---------------- feature gather + split ----------------
__global__ void gather_kernel(const float* __restrict__ x,
                              const int* __restrict__ sL,
                              const int* __restrict__ sC) {
    int idx = blockIdx.x * 256 + threadIdx.x;
    if (idx >= M_TOT * K1) return;
    int m = idx / K1;
    int k = idx - m * K1;
    int b = m >> 8;                 // NP = 256
    int s_l = sL[m];
    float v;
    if (k < KPATCH) {
        int l = k >> 4, c = k & 15;
        int s_c = sC[m];
        // no wrap: s_l + l < L, s_c + c < C by construction
        v = x[(b * L_ + s_l + l) * C_ + s_c + c];
    } else {
        int l = k - KPATCH;
        v = (float)(s_l + l) * 1e-3f;   // t = (sL+l)/FS
    }
    split_bf16(v, g_fh[idx], g_fl[idx]);
}

// ---------------- bf16-split GEMM: C[M,N] = A[M,K] * B[N,K]^T (+bias, [silu]) ----------------
// OUTMODE 1: silu, write hi/lo bf16 (for h). OUTMODE 0: write fp32 (final output).
#define BM 64
#define BN 128
#define BK 32
#define SST 40   // padded smem row stride (elems): 80B, 16B-aligned, conflict-free frag loads

__device__ __forceinline__ void mma16816(float* c, const uint32_t* a, uint32_t b0, uint32_t b1) {
    asm volatile(
        "mma.sync.aligned.m16n8k16.row.col.f32.bf16.bf16.f32 "
        "{%0,%1,%2,%3}, {%4,%5,%6,%7}, {%8,%9}, {%0,%1,%2,%3};\n"
        : "+f"(c[0]), "+f"(c[1]), "+f"(c[2]), "+f"(c[3])
        : "r"(a[0]), "r"(a[1]), "r"(a[2]), "r"(a[3]), "r"(b0), "r"(b1));
}

template <int OUTMODE>
__global__ __launch_bounds__(256, 2) void gemm_split_kernel(
    const __nv_bfloat16* __restrict__ Ah, const __nv_bfloat16* __restrict__ Al,
    const __nv_bfloat16* __restrict__ Bh, const __nv_bfloat16* __restrict__ Bl,
    const float* __restrict__ bias,
    float* __restrict__ outF,
    __nv_bfloat16* __restrict__ outHi, __nv_bfloat16* __restrict__ outLo,
    int K, int N)
{
    __shared__ __nv_bfloat16 sAh[BM][SST], sAl[BM][SST];
    __shared__ __nv_bfloat16 sBh[BN][SST], sBl[BN][SST];

    const int tid  = threadIdx.x;
    const int warp = tid >> 5, lane = tid & 31;
    const int wm = warp >> 2, wn = warp & 3;   // 2 x 4 warp grid
    const int g  = lane >> 2, t4 = lane & 3;
    const int m0 = blockIdx.y * BM;
    const int n0 = blockIdx.x * BN;

    // staging load addressing
    const int arow = tid >> 2;            // 0..63
    const int acol = (tid & 3) * 8;       // 0,8,16,24
    const int brow = tid >> 1;            // 0..127
    const int bcol = (tid & 1) * 16;      // 0,16

    float acc[2][4][4];
#pragma unroll
    for (int i = 0; i < 2; ++i)
#pragma unroll
        for (int j = 0; j < 4; ++j)
#pragma unroll
            for (int r = 0; r < 4; ++r) acc[i][j][r] = 0.f;

    const int steps = K / BK;
    for (int s = 0; s < steps; ++s) {
        const int k0 = s * BK;
        // global -> regs
        const uint4 ra_h = *reinterpret_cast<const uint4*>(Ah + (m0 + arow) * K + k0 + acol);
        const uint4 ra_l = *reinterpret_cast<const uint4*>(Al + (m0 + arow) * K + k0 + acol);
        const uint4* pbh = reinterpret_cast<const uint4*>(Bh + (n0 + brow) * K + k0 + bcol);
        const uint4* pbl = reinterpret_cast<const uint4*>(Bl + (n0 + brow) * K + k0 + bcol);
        const uint4 rb_h0 = pbh[0], rb_h1 = pbh[1];
        const uint4 rb_l0 = pbl[0], rb_l1 = pbl[1];

        __syncthreads();   // previous iteration's mma reads done
        *reinterpret_cast<uint4*>(&sAh[arow][acol]) = ra_h;
        *reinterpret_cast<uint4*>(&sAl[arow][acol]) = ra_l;
        *reinterpret_cast<uint4*>(&sBh[brow][bcol]) = rb_h0;
        *reinterpret_cast<uint4*>(&sBh[brow][bcol + 8]) = rb_h1;
        *reinterpret_cast<uint4*>(&sBl[brow][bcol]) = rb_l0;
        *reinterpret_cast<uint4*>(&sBl[brow][bcol + 8]) = rb_l1;
        __syncthreads();

#pragma unroll
        for (int ks = 0; ks < 2; ++ks) {
            const int kb = ks * 16;
            uint32_t afh[2][4], afl[2][4];
#pragma unroll
            for (int mt = 0; mt < 2; ++mt) {
                const int r = wm * 32 + mt * 16 + g;
                afh[mt][0] = *reinterpret_cast<const uint32_t*>(&sAh[r][kb + 2 * t4]);
                afh[mt][1] = *reinterpret_cast<const uint32_t*>(&sAh[r + 8][kb + 2 * t4]);
                afh[mt][2] = *reinterpret_cast<const uint32_t*>(&sAh[r][kb + 2 * t4 + 8]);
                afh[mt][3] = *reinterpret_cast<const uint32_t*>(&sAh[r + 8][kb + 2 * t4 + 8]);
                afl[mt][0] = *reinterpret_cast<const uint32_t*>(&sAl[r][kb + 2 * t4]);
                afl[mt][1] = *reinterpret_cast<const uint32_t*>(&sAl[r + 8][kb + 2 * t4]);
                afl[mt][2] = *reinterpret_cast<const uint32_t*>(&sAl[r][kb + 2 * t4 + 8]);
                afl[mt][3] = *reinterpret_cast<const uint32_t*>(&sAl[r + 8][kb + 2 * t4 + 8]);
            }
#pragma unroll
            for (int nt = 0; nt < 4; ++nt) {
                const int c = wn * 32 + nt * 8 + g;
                const uint32_t bh0 = *reinterpret_cast<const uint32_t*>(&sBh[c][kb + 2 * t4]);
                const uint32_t bh1 = *reinterpret_cast<const uint32_t*>(&sBh[c][kb + 2 * t4 + 8]);
                const uint32_t bl0 = *reinterpret_cast<const uint32_t*>(&sBl[c][kb + 2 * t4]);
                const uint32_t bl1 = *reinterpret_cast<const uint32_t*>(&sBl[c][kb + 2 * t4 + 8]);
#pragma unroll
                for (int mt = 0; mt < 2; ++mt) {
                    mma16816(acc[mt][nt], afh[mt], bh0, bh1);  // hi*hi
                    mma16816(acc[mt][nt], afl[mt], bh0, bh1);  // lo*hi
                    mma16816(acc[mt][nt], afh[mt], bl0, bl1);  // hi*lo
                }
            }
        }
    }

    // epilogue
#pragma unroll
    for (int mt = 0; mt < 2; ++mt) {
#pragma unroll
        for (int nt = 0; nt < 4; ++nt) {
            const int row0 = m0 + wm * 32 + mt * 16 + g;
            const int col  = n0 + wn * 32 + nt * 8 + 2 * t4;
            const float bx = bias[col], by = bias[col + 1];
            float v00 = acc[mt][nt][0] + bx;
            float v01 = acc[mt][nt][1] + by;
            float v10 = acc[mt][nt][2] + bx;
            float v11 = acc[mt][nt][3] + by;
            if (OUTMODE == 1) {
                v00 = v00 * (1.f / (1.f + __expf(-v00)));
                v01 = v01 * (1.f / (1.f + __expf(-v01)));
                v10 = v10 * (1.f / (1.f + __expf(-v10)));
                v11 = v11 * (1.f / (1.f + __expf(-v11)));
                __nv_bfloat16 h0, l0, h1, l1;
                split_bf16(v00, h0, l0); split_bf16(v01, h1, l1);
                __nv_bfloat162 ph, pl; ph.x = h0; ph.y = h1; pl.x = l0; pl.y = l1;
                *reinterpret_cast<__nv_bfloat162*>(&outHi[row0 * N + col]) = ph;
                *reinterpret_cast<__nv_bfloat162*>(&outLo[row0 * N + col]) = pl;
                split_bf16(v10, h0, l0); split_bf16(v11, h1, l1);
                ph.x = h0; ph.y = h1; pl.x = l0; pl.y = l1;
                *reinterpret_cast<__nv_bfloat162*>(&outHi[(row0 + 8) * N + col]) = ph;
                *reinterpret_cast<__nv_bfloat162*>(&outLo[(row0 + 8) * N + col]) = pl;
            } else {
                float2 r0; r0.x = v00; r0.y = v01;
                float2 r1; r1.x = v10; r1.y = v11;
                *reinterpret_cast<float2*>(&outF[row0 * N + col]) = r0;
                *reinterpret_cast<float2*>(&outF[(row0 + 8) * N + col]) = r1;
            }
        }
    }
}

// ---------------- launch ----------------
extern "C" void kernel_launch(void* const* d_in, const int* in_sizes, int n_in,
                              void* d_out, int out_size) {
    const float* x  = (const float*)d_in[0];
    const int* sL   = (const int*)d_in[1];
    const int* sC   = (const int*)d_in[2];
    const float* w1 = (const float*)d_in[3];
    const float* b1 = (const float*)d_in[4];
    const float* w2 = (const float*)d_in[5];
    const float* b2 = (const float*)d_in[6];
    float* out = (float*)d_out;

    // resolve device-global scratch addresses
    __nv_bfloat16 *w1h, *w1l, *w2h, *w2l, *fh, *fl, *hh, *hl;
    cudaGetSymbolAddress((void**)&w1h, g_w1h);
    cudaGetSymbolAddress((void**)&w1l, g_w1l);
    cudaGetSymbolAddress((void**)&w2h, g_w2h);
    cudaGetSymbolAddress((void**)&w2l, g_w2l);
    cudaGetSymbolAddress((void**)&fh,  g_fh);
    cudaGetSymbolAddress((void**)&fl,  g_fl);
    cudaGetSymbolAddress((void**)&hh,  g_hh);
    cudaGetSymbolAddress((void**)&hl,  g_hl);

    // 1) weight fold + split
    prep_w1_kernel<<<(OUT_ * K1 + 255) / 256, 256>>>(w1);
    prep_w2_kernel<<<(OUT_ * OUT_ + 255) / 256, 256>>>(w2);
    // 2) feature gather + split
    gather_kernel<<<(M_TOT * K1 + 255) / 256, 256>>>(x, sL, sC);
    // 3) GEMM1: h = silu(feats @ w1eff^T + b1) -> bf16 hi/lo
    {
        dim3 grid(OUT_ / BN, M_TOT / BM);   // (4, 128)
        gemm_split_kernel<1><<<grid, 256>>>(fh, fl, w1h, w1l, b1,
                                            nullptr, hh, hl, K1, OUT_);
    }
    // 4) GEMM2: out = h @ w2^T + b2 -> fp32
    {
        dim3 grid(OUT_ / BN, M_TOT / BM);
        gemm_split_kernel<0><<<grid, 256>>>(hh, hl, w2h, w2l, b2,
                                            out, nullptr, nullptr, OUT_, OUT_);
    }
    (void)in_sizes; (void)n_in; (void)out_size;
}

// round 16
// speedup vs baseline: 1.0019x; 1.0019x over previous
#include <cuda_runtime.h>
#include <cuda_bf16.h>
#include <cstdint>

// Problem constants
#define B_    32
#define L_    4096
#define C_    64
#define PL_   64
#define PC_   16
#define NP_   256
#define OUT_  512
#define DIN   2048              // PL * 2*PC (original w1 inner dim)
#define M_TOT 8192              // B * NP
#define K1    1088              // PL*PC (patch) + PL (folded time feature)
#define KPATCH 1024             // PL*PC

// ---------------- device scratch (no allocations allowed) ----------------
__device__ __nv_bfloat16 g_w1h[OUT_ * K1];
__device__ __nv_bfloat16 g_w1l[OUT_ * K1];
__device__ __nv_bfloat16 g_w2h[OUT_ * OUT_];
__device__ __nv_bfloat16 g_w2l[OUT_ * OUT_];
__device__ __nv_bfloat16 g_fh[M_TOT * K1];
__device__ __nv_bfloat16 g_fl[M_TOT * K1];
__device__ __nv_bfloat16 g_hh[M_TOT * OUT_];
__device__ __nv_bfloat16 g_hl[M_TOT * OUT_];

__device__ __forceinline__ void split_bf16(float v, __nv_bfloat16& hi, __nv_bfloat16& lo) {
    hi = __float2bfloat16(v);                       // RN
    lo = __float2bfloat16(v - __bfloat162float(hi)); // residual (exact subtract)
}

// ---------------- weight prep: fold time columns, split hi/lo ----------------
__global__ void prep_w1_kernel(const float* __restrict__ w1) {
    int idx = blockIdx.x * 256 + threadIdx.x;
    if (idx >= OUT_ * K1) return;
    int o = idx / K1;
    int k = idx - o * K1;
    float v;
    if (k < KPATCH) {
        int l = k >> 4, c = k & 15;
        v = w1[o * DIN + l * 32 + c];
    } else {
        int l = k - KPATCH;
        const float* p = w1 + o * DIN + l * 32 + 16;
        float s = 0.f;
#pragma unroll
        for (int c = 0; c < 16; ++c) s += p[c];
        v = s;
    }
    split_bf16(v, g_w1h[idx], g_w1l[idx]);
}

__global__ void prep_w2_kernel(const float* __restrict__ w2) {
    int idx = blockIdx.x * 256 + threadIdx.x;
    if (idx >= OUT_ * OUT_) return;
    split_bf16(w2[idx], g_w2h[idx], g_w2l[idx]);
}

// ---------------- feature gather + split ----------------
__global__ void gather_kernel(const float* __restrict__ x,
                              const int* __restrict__ sL,
                              const int* __restrict__ sC) {
    int idx = blockIdx.x * 256 + threadIdx.x;
    if (idx >= M_TOT * K1) return;
    int m = idx / K1;
    int k = idx - m * K1;
    int b = m >> 8;                 // NP = 256
    int s_l = sL[m];
    float v;
    if (k < KPATCH) {
        int l = k >> 4, c = k & 15;
        int s_c = sC[m];
        // no wrap: s_l + l < L, s_c + c < C by construction
        v = x[(b * L_ + s_l + l) * C_ + s_c + c];
    } else {
        int l = k - KPATCH;
        v = (float)(s_l + l) * 1e-3f;   // t = (sL+l)/FS
    }
    split_bf16(v, g_fh[idx], g_fl[idx]);
}

// ---------------- bf16-split GEMM: C[M,N] = A[M,K] * B[N,K]^T (+bias, [silu]) ----------------
// OUTMODE 1: silu, write hi/lo bf16 (for h). OUTMODE 0: write fp32 (final output).
#define BM 64
#define BN 128
#define BK 32
#define SST 40   // padded smem row stride (elems): 80B, 16B-aligned, conflict-free frag loads

__device__ __forceinline__ void mma16816(float* c, const uint32_t* a, uint32_t b0, uint32_t b1) {
    asm volatile(
        "mma.sync.aligned.m16n8k16.row.col.f32.bf16.bf16.f32 "
        "{%0,%1,%2,%3}, {%4,%5,%6,%7}, {%8,%9}, {%0,%1,%2,%3};\n"
        : "+f"(c[0]), "+f"(c[1]), "+f"(c[2]), "+f"(c[3])
        : "r"(a[0]), "r"(a[1]), "r"(a[2]), "r"(a[3]), "r"(b0), "r"(b1));
}

template <int OUTMODE>
__global__ __launch_bounds__(256, 2) void gemm_split_kernel(
    const __nv_bfloat16* __restrict__ Ah, const __nv_bfloat16* __restrict__ Al,
    const __nv_bfloat16* __restrict__ Bh, const __nv_bfloat16* __restrict__ Bl,
    const float* __restrict__ bias,
    float* __restrict__ outF,
    __nv_bfloat16* __restrict__ outHi, __nv_bfloat16* __restrict__ outLo,
    int K, int N)
{
    __shared__ __nv_bfloat16 sAh[BM][SST], sAl[BM][SST];
    __shared__ __nv_bfloat16 sBh[BN][SST], sBl[BN][SST];

    const int tid  = threadIdx.x;
    const int warp = tid >> 5, lane = tid & 31;
    const int wm = warp >> 2, wn = warp & 3;   // 2 x 4 warp grid
    const int g  = lane >> 2, t4 = lane & 3;
    const int m0 = blockIdx.y * BM;
    const int n0 = blockIdx.x * BN;

    // staging load addressing
    const int arow = tid >> 2;            // 0..63
    const int acol = (tid & 3) * 8;       // 0,8,16,24
    const int brow = tid >> 1;            // 0..127
    const int bcol = (tid & 1) * 16;      // 0,16

    float acc[2][4][4];
#pragma unroll
    for (int i = 0; i < 2; ++i)
#pragma unroll
        for (int j = 0; j < 4; ++j)
#pragma unroll
            for (int r = 0; r < 4; ++r) acc[i][j][r] = 0.f;

    const int steps = K / BK;
    for (int s = 0; s < steps; ++s) {
        const int k0 = s * BK;
        // global -> regs
        const uint4 ra_h = *reinterpret_cast<const uint4*>(Ah + (m0 + arow) * K + k0 + acol);
        const uint4 ra_l = *reinterpret_cast<const uint4*>(Al + (m0 + arow) * K + k0 + acol);
        const uint4* pbh = reinterpret_cast<const uint4*>(Bh + (n0 + brow) * K + k0 + bcol);
        const uint4* pbl = reinterpret_cast<const uint4*>(Bl + (n0 + brow) * K + k0 + bcol);
        const uint4 rb_h0 = pbh[0], rb_h1 = pbh[1];
        const uint4 rb_l0 = pbl[0], rb_l1 = pbl[1];

        __syncthreads();   // previous iteration's mma reads done
        *reinterpret_cast<uint4*>(&sAh[arow][acol]) = ra_h;
        *reinterpret_cast<uint4*>(&sAl[arow][acol]) = ra_l;
        *reinterpret_cast<uint4*>(&sBh[brow][bcol]) = rb_h0;
        *reinterpret_cast<uint4*>(&sBh[brow][bcol + 8]) = rb_h1;
        *reinterpret_cast<uint4*>(&sBl[brow][bcol]) = rb_l0;
        *reinterpret_cast<uint4*>(&sBl[brow][bcol + 8]) = rb_l1;
        __syncthreads();

#pragma unroll
        for (int ks = 0; ks < 2; ++ks) {
            const int kb = ks * 16;
            uint32_t afh[2][4], afl[2][4];
#pragma unroll
            for (int mt = 0; mt < 2; ++mt) {
                const int r = wm * 32 + mt * 16 + g;
                afh[mt][0] = *reinterpret_cast<const uint32_t*>(&sAh[r][kb + 2 * t4]);
                afh[mt][1] = *reinterpret_cast<const uint32_t*>(&sAh[r + 8][kb + 2 * t4]);
                afh[mt][2] = *reinterpret_cast<const uint32_t*>(&sAh[r][kb + 2 * t4 + 8]);
                afh[mt][3] = *reinterpret_cast<const uint32_t*>(&sAh[r + 8][kb + 2 * t4 + 8]);
                afl[mt][0] = *reinterpret_cast<const uint32_t*>(&sAl[r][kb + 2 * t4]);
                afl[mt][1] = *reinterpret_cast<const uint32_t*>(&sAl[r + 8][kb + 2 * t4]);
                afl[mt][2] = *reinterpret_cast<const uint32_t*>(&sAl[r][kb + 2 * t4 + 8]);
                afl[mt][3] = *reinterpret_cast<const uint32_t*>(&sAl[r + 8][kb + 2 * t4 + 8]);
            }
#pragma unroll
            for (int nt = 0; nt < 4; ++nt) {
                const int c = wn * 32 + nt * 8 + g;
                const uint32_t bh0 = *reinterpret_cast<const uint32_t*>(&sBh[c][kb + 2 * t4]);
                const uint32_t bh1 = *reinterpret_cast<const uint32_t*>(&sBh[c][kb + 2 * t4 + 8]);
                const uint32_t bl0 = *reinterpret_cast<const uint32_t*>(&sBl[c][kb + 2 * t4]);
                const uint32_t bl1 = *reinterpret_cast<const uint32_t*>(&sBl[c][kb + 2 * t4 + 8]);
#pragma unroll
                for (int mt = 0; mt < 2; ++mt) {
                    mma16816(acc[mt][nt], afh[mt], bh0, bh1);  // hi*hi
                    mma16816(acc[mt][nt], afl[mt], bh0, bh1);  // lo*hi
                    mma16816(acc[mt][nt], afh[mt], bl0, bl1);  // hi*lo
                }
            }
        }
    }

    // epilogue
#pragma unroll
    for (int mt = 0; mt < 2; ++mt) {
#pragma unroll
        for (int nt = 0; nt < 4; ++nt) {
            const int row0 = m0 + wm * 32 + mt * 16 + g;
            const int col  = n0 + wn * 32 + nt * 8 + 2 * t4;
            const float bx = bias[col], by = bias[col + 1];
            float v00 = acc[mt][nt][0] + bx;
            float v01 = acc[mt][nt][1] + by;
            float v10 = acc[mt][nt][2] + bx;
            float v11 = acc[mt][nt][3] + by;
            if (OUTMODE == 1) {
                v00 = v00 * (1.f / (1.f + __expf(-v00)));
                v01 = v01 * (1.f / (1.f + __expf(-v01)));
                v10 = v10 * (1.f / (1.f + __expf(-v10)));
                v11 = v11 * (1.f / (1.f + __expf(-v11)));
                __nv_bfloat16 h0, l0, h1, l1;
                split_bf16(v00, h0, l0); split_bf16(v01, h1, l1);
                __nv_bfloat162 ph, pl; ph.x = h0; ph.y = h1; pl.x = l0; pl.y = l1;
                *reinterpret_cast<__nv_bfloat162*>(&outHi[row0 * N + col]) = ph;
                *reinterpret_cast<__nv_bfloat162*>(&outLo[row0 * N + col]) = pl;
                split_bf16(v10, h0, l0); split_bf16(v11, h1, l1);
                ph.x = h0; ph.y = h1; pl.x = l0; pl.y = l1;
                *reinterpret_cast<__nv_bfloat162*>(&outHi[(row0 + 8) * N + col]) = ph;
                *reinterpret_cast<__nv_bfloat162*>(&outLo[(row0 + 8) * N + col]) = pl;
            } else {
                float2 r0; r0.x = v00; r0.y = v01;
                float2 r1; r1.x = v10; r1.y = v11;
                *reinterpret_cast<float2*>(&outF[row0 * N + col]) = r0;
                *reinterpret_cast<float2*>(&outF[(row0 + 8) * N + col]) = r1;
            }
        }
    }
}

// ---------------- launch ----------------
extern "C" void kernel_launch(void* const* d_in, const int* in_sizes, int n_in,
                              void* d_out, int out_size) {
    const float* x  = (const float*)d_in[0];
    const int* sL   = (const int*)d_in[1];
    const int* sC   = (const int*)d_in[2];
    const float* w1 = (const float*)d_in[3];
    const float* b1 = (const float*)d_in[4];
    const float* w2 = (const float*)d_in[5];
    const float* b2 = (const float*)d_in[6];
    float* out = (float*)d_out;

    // resolve device-global scratch addresses
    __nv_bfloat16 *w1h, *w1l, *w2h, *w2l, *fh, *fl, *hh, *hl;
    cudaGetSymbolAddress((void**)&w1h, g_w1h);
    cudaGetSymbolAddress((void**)&w1l, g_w1l);
    cudaGetSymbolAddress((void**)&w2h, g_w2h);
    cudaGetSymbolAddress((void**)&w2l, g_w2l);
    cudaGetSymbolAddress((void**)&fh,  g_fh);
    cudaGetSymbolAddress((void**)&fl,  g_fl);
    cudaGetSymbolAddress((void**)&hh,  g_hh);
    cudaGetSymbolAddress((void**)&hl,  g_hl);

    // 1) weight fold + split
    prep_w1_kernel<<<(OUT_ * K1 + 255) / 256, 256>>>(w1);
    prep_w2_kernel<<<(OUT_ * OUT_ + 255) / 256, 256>>>(w2);
    // 2) feature gather + split
    gather_kernel<<<(M_TOT * K1 + 255) / 256, 256>>>(x, sL, sC);
    // 3) GEMM1: h = silu(feats @ w1eff^T + b1) -> bf16 hi/lo
    {
        dim3 grid(OUT_ / BN, M_TOT / BM);   // (4, 128)
        gemm_split_kernel<1><<<grid, 256>>>(fh, fl, w1h, w1l, b1,
                                            nullptr, hh, hl, K1, OUT_);
    }
    // 4) GEMM2: out = h @ w2^T + b2 -> fp32
    {
        dim3 grid(OUT_ / BN, M_TOT / BM);
        gemm_split_kernel<0><<<grid, 256>>>(hh, hl, w2h, w2l, b2,
                                            out, nullptr, nullptr, OUT_, OUT_);
    }
    (void)in_sizes; (void)n_in; (void)out_size;
}